// round 16
// baseline (speedup 1.0000x reference)
#include <cuda_runtime.h>
#include <cuda_fp16.h>
#include <math.h>

#define T_STEPS 120
#define F_IN    180
#define H       128
#define G4      512
#define MAX_B   2048

// ---------------- static scratch ----------------
__device__ __half g_xproj[(size_t)MAX_B * T_STEPS * G4];   // fp16 projections (in-place reuse)
__device__ float  g_biasp0[G4],  g_biasp1[G4];
__device__ __align__(16) __half g_wfh0[G4 * H], g_wfh1[G4 * H];   // Whh fp16 m16n8k16 B-frags
__device__ __align__(16) __half g_wifh0[G4 * H], g_wifh1[G4 * H]; // wih fp16 m16n8k16 B-frags

// ---------------- helpers ----------------
__device__ __forceinline__ void mma16h(float* c, unsigned a0, unsigned a1, unsigned a2, unsigned a3,
                                       unsigned b0, unsigned b1) {
    asm volatile("mma.sync.aligned.m16n8k16.row.col.f32.f16.f16.f32 "
                 "{%0,%1,%2,%3}, {%4,%5,%6,%7}, {%8,%9}, {%0,%1,%2,%3};"
                 : "+f"(c[0]), "+f"(c[1]), "+f"(c[2]), "+f"(c[3])
                 : "r"(a0), "r"(a1), "r"(a2), "r"(a3), "r"(b0), "r"(b1));
}
__device__ __forceinline__ void ldsm4(unsigned& a0, unsigned& a1, unsigned& a2, unsigned& a3,
                                      unsigned addr) {
    asm volatile("ldmatrix.sync.aligned.m8n8.x4.shared.b16 {%0,%1,%2,%3}, [%4];"
                 : "=r"(a0), "=r"(a1), "=r"(a2), "=r"(a3) : "r"(addr));
}
__device__ __forceinline__ float tanh_ap(float x) {
    float y; asm("tanh.approx.f32 %0, %1;" : "=f"(y) : "f"(x)); return y;
}
__device__ __forceinline__ float sig_ap(float x) {
    return fmaf(0.5f, tanh_ap(0.5f * x), 0.5f);
}

// ---------------- prep: combine bias; pack Whh AND wih as fp16 m16n8k16 B-frags ----------------
__global__ void prep_kernel(const float* __restrict__ wih, const float* __restrict__ bih,
                            const float* __restrict__ bhh, const float* __restrict__ whh,
                            float* __restrict__ biasp, __half* __restrict__ wfh,
                            __half* __restrict__ wifh)
{
    int i = blockIdx.x * 256 + threadIdx.x;
    if (i < G4 * H) {
        int n = i >> 7, k = i & 127;
        if (k == 0) {
            int np = ((n & 127) << 2) | (n >> 7);
            biasp[np] = bih[n] + bhh[n];
        }
        int v2 = i & 7, lane = (i >> 3) & 31, p = (i >> 8) & 3, j = (i >> 10) & 3, w = i >> 12;
        int ks = 2 * p + (v2 >> 2);
        int kk = ks * 16 + (lane & 3) * 2 + (v2 & 1) + ((v2 >> 1) & 1) * 8;
        int np = w * 32 + j * 8 + (lane >> 2);
        int orig = ((np & 3) << 7) | (np >> 2);
        wfh [i] = __float2half_rn(whh[orig * H + kk]);
        wifh[i] = __float2half_rn(wih[orig * H + kk]);
    }
}

#define SA  40
#define S2  136

// ---------------- fused FC+BN+LeakyReLU -> layer-0 projection (all fp16 mma) ----------------
__global__ void __launch_bounds__(256)
fc_proj_fused(const float* __restrict__ x, const float* __restrict__ W,
              const __half* __restrict__ Wf, __half* __restrict__ C,
              const float* __restrict__ fcb, const float* __restrict__ bng,
              const float* __restrict__ bnb, const float* __restrict__ bnm,
              const float* __restrict__ bnv, const float* __restrict__ biasp)
{
    extern __shared__ __align__(16) char fsm[];
    __half* Ah = (__half*)fsm;              // [2][128*SA]
    __half* Bh = Ah + 2 * 128 * SA;         // [2][128*SA]
    __half* hp = Bh + 2 * 128 * SA;         // [128][S2]
    __shared__ int rowbase[128];

    const int tid  = threadIdx.x;
    const int lane = tid & 31, warp = tid >> 5;
    const int g = lane >> 2, t = lane & 3;
    const int wm = warp & 3, wn = warp >> 2;
    const int m0 = blockIdx.x * 128;

    if (tid < 128) {
        int m = m0 + tid; int b = m / T_STEPS;
        rowbase[tid] = b * (F_IN * T_STEPS) + (m - b * T_STEPS);
    }
    __syncthreads();

    const int r  = tid >> 1;
    const int hf = tid & 1;
    const int nc = 6;

    __half2 av2[8], wv2[8];
    auto LOAD = [&](int kc) {
#pragma unroll
        for (int i = 0; i < 8; i++) {
            int k = kc + hf * 16 + 2 * i;
            float x0 = (k     < F_IN) ? __ldg(x + rowbase[r] + k * T_STEPS)       : 0.f;
            float x1 = (k + 1 < F_IN) ? __ldg(x + rowbase[r] + (k + 1) * T_STEPS) : 0.f;
            av2[i] = __floats2half2_rn(x0, x1);
            float w0 = (k     < F_IN) ? __ldg(W + r * F_IN + k)     : 0.f;
            float w1 = (k + 1 < F_IN) ? __ldg(W + r * F_IN + k + 1) : 0.f;
            wv2[i] = __floats2half2_rn(w0, w1);
        }
    };
    auto STORE = [&](int s) {
#pragma unroll
        for (int i = 0; i < 8; i++) {
            *(__half2*)&Ah[s * 128 * SA + r * SA + hf * 16 + 2 * i] = av2[i];
            *(__half2*)&Bh[s * 128 * SA + r * SA + hf * 16 + 2 * i] = wv2[i];
        }
    };

    float acc[2][8][4];
#pragma unroll
    for (int mi = 0; mi < 2; mi++)
#pragma unroll
        for (int j = 0; j < 8; j++)
#pragma unroll
            for (int q = 0; q < 4; q++) acc[mi][j][q] = 0.f;

    const unsigned ah_smem = (unsigned)__cvta_generic_to_shared(Ah);
    const unsigned lm_a    = ah_smem + (unsigned)((lane & 15) * SA * 2 + (lane >> 4) * 16);

    LOAD(0); STORE(0); __syncthreads();

    for (int c = 0; c < nc; c++) {
        if (c + 1 < nc) LOAD((c + 1) * 32);
        const unsigned abuf = lm_a + (unsigned)((c & 1) * 128 * SA * 2);
        const __half* bs = Bh + (c & 1) * 128 * SA;
#pragma unroll
        for (int kq = 0; kq < 2; kq++) {
            unsigned a[2][4];
#pragma unroll
            for (int mi = 0; mi < 2; mi++)
                ldsm4(a[mi][0], a[mi][1], a[mi][2], a[mi][3],
                      abuf + (unsigned)((wm * 32 + mi * 16) * SA * 2 + kq * 32));
#pragma unroll
            for (int j = 0; j < 8; j++) {
                int row = wn * 64 + j * 8 + g;
                unsigned b0 = *(const unsigned*)&bs[row * SA + kq * 16 + 2 * t];
                unsigned b1 = *(const unsigned*)&bs[row * SA + kq * 16 + 2 * t + 8];
#pragma unroll
                for (int mi = 0; mi < 2; mi++)
                    mma16h(acc[mi][j], a[mi][0], a[mi][1], a[mi][2], a[mi][3], b0, b1);
            }
        }
        if (c + 1 < nc) STORE((c + 1) & 1);
        __syncthreads();
    }

#pragma unroll
    for (int j = 0; j < 8; j++) {
        int col = wn * 64 + j * 8 + 2 * t;
        float s0 = bng[col]     * rsqrtf(bnv[col]     + 1e-5f);
        float s1 = bng[col + 1] * rsqrtf(bnv[col + 1] + 1e-5f);
        float be0 = (fcb[col]     - bnm[col]    ) * s0 + bnb[col];
        float be1 = (fcb[col + 1] - bnm[col + 1]) * s1 + bnb[col + 1];
#pragma unroll
        for (int mi = 0; mi < 2; mi++) {
            int row = wm * 32 + mi * 16 + g;
            float v0 = acc[mi][j][0] * s0 + be0;
            float v1 = acc[mi][j][1] * s1 + be1;
            float v2 = acc[mi][j][2] * s0 + be0;
            float v3 = acc[mi][j][3] * s1 + be1;
            v0 = (v0 >= 0.f) ? v0 : 0.01f * v0;
            v1 = (v1 >= 0.f) ? v1 : 0.01f * v1;
            v2 = (v2 >= 0.f) ? v2 : 0.01f * v2;
            v3 = (v3 >= 0.f) ? v3 : 0.01f * v3;
            *(__half2*)&hp[(row    ) * S2 + col] = __floats2half2_rn(v0, v1);
            *(__half2*)&hp[(row + 8) * S2 + col] = __floats2half2_rn(v2, v3);
        }
    }
    __syncthreads();

    const uint4* wf4 = (const uint4*)Wf;
    const unsigned hp_smem = (unsigned)__cvta_generic_to_shared(hp);
    const unsigned lm_h    = hp_smem + (unsigned)((lane & 15) * S2 * 2 + (lane >> 4) * 16);
#pragma unroll 1
    for (int nch = 0; nch < 4; nch++) {
        float a2[2][8][4];
#pragma unroll
        for (int mi = 0; mi < 2; mi++)
#pragma unroll
            for (int j = 0; j < 8; j++)
#pragma unroll
                for (int q = 0; q < 4; q++) a2[mi][j][q] = 0.f;

#pragma unroll
        for (int p = 0; p < 4; p++) {
            unsigned e[2][4], o[2][4];
#pragma unroll
            for (int mi = 0; mi < 2; mi++) {
                unsigned rbase = lm_h + (unsigned)((wm * 32 + mi * 16) * S2 * 2);
                ldsm4(e[mi][0], e[mi][1], e[mi][2], e[mi][3], rbase + (2 * p    ) * 32u);
                ldsm4(o[mi][0], o[mi][1], o[mi][2], o[mi][3], rbase + (2 * p + 1) * 32u);
            }
#pragma unroll
            for (int j = 0; j < 8; j++) {
                int nt = nch * 16 + wn * 8 + j;
                uint4 b = __ldg(wf4 + ((size_t)nt * 4 + p) * 32 + lane);
#pragma unroll
                for (int mi = 0; mi < 2; mi++) {
                    mma16h(a2[mi][j], e[mi][0], e[mi][1], e[mi][2], e[mi][3], b.x, b.y);
                    mma16h(a2[mi][j], o[mi][0], o[mi][1], o[mi][2], o[mi][3], b.z, b.w);
                }
            }
        }
#pragma unroll
        for (int j = 0; j < 8; j++) {
            int col = nch * 128 + wn * 64 + j * 8 + 2 * t;
            float be0 = __ldg(biasp + col);
            float be1 = __ldg(biasp + col + 1);
#pragma unroll
            for (int mi = 0; mi < 2; mi++) {
                int row = m0 + wm * 32 + mi * 16 + g;
                *(__half2*)(C + (size_t)row * G4 + col) =
                    __floats2half2_rn(a2[mi][j][0] + be0, a2[mi][j][1] + be1);
                *(__half2*)(C + (size_t)(row + 8) * G4 + col) =
                    __floats2half2_rn(a2[mi][j][2] + be0, a2[mi][j][3] + be1);
            }
        }
    }
}

#define SHh    136
#define HBUF_B (16 * SHh * 2)

// ---------------- plain persistent fp16 LSTM (layer 1) ----------------
__global__ void __launch_bounds__(512)
lstm_plain(const __half* __restrict__ xproj, const __half* __restrict__ wfh,
           float* __restrict__ hlast)
{
    extern __shared__ unsigned smx[];
    __half* h_buf = (__half*)smx;
    uint4*  swf   = (uint4*)((char*)smx + 2 * HBUF_B);

    const int tid  = threadIdx.x, lane = tid & 31, w = tid >> 5;
    const int g = lane >> 2, t = lane & 3;
    const int odd = t & 1;
    const int b0 = blockIdx.x * 16;
    uint4* swfw = swf + (size_t)w * 512;

    {
        const uint4* src = (const uint4*)wfh + (size_t)w * 512;
        for (int idx = lane; idx < 512; idx += 32)
            swfw[idx] = __ldg(src + idx);
    }
    for (int i = tid; i < (2 * HBUF_B) / 4; i += 512) smx[i] = 0u;
    __syncthreads();

    float c_reg[4] = {0.f, 0.f, 0.f, 0.f};
    const int row_pw = g + odd * 8;
    const int hh0    = w * 8 + (t >> 1);
    const __half* xr0 = xproj + (size_t)(b0 + g    ) * T_STEPS * G4;
    const __half* xr1 = xproj + (size_t)(b0 + g + 8) * T_STEPS * G4;
    const int colbase = w * 32 + 2 * t;

    const unsigned hb_smem = (unsigned)__cvta_generic_to_shared(h_buf);
    const unsigned lmoff = hb_smem + (unsigned)((lane & 15) * SHh * 2 + (lane >> 4) * 16);

    __half2 p0[4], p1[4];
#pragma unroll
    for (int j = 0; j < 4; j++) {
        p0[j] = *(const __half2*)(xr0 + colbase + j * 8);
        p1[j] = *(const __half2*)(xr1 + colbase + j * 8);
    }

    int cur = 0;
    for (int ts = 0; ts < T_STEPS; ts++) {
        __half*        hnb   = h_buf + (cur ^ 1) * (16 * SHh);
        const unsigned abase = lmoff + (unsigned)(cur * HBUF_B);
        float acc[4][4];
#pragma unroll
        for (int j = 0; j < 4; j++) {
            float2 f0 = __half22float2(p0[j]);
            float2 f1 = __half22float2(p1[j]);
            acc[j][0] = f0.x; acc[j][1] = f0.y;
            acc[j][2] = f1.x; acc[j][3] = f1.y;
        }
        {
            int tn = (ts + 1 < T_STEPS) ? ts + 1 : ts;
#pragma unroll
            for (int j = 0; j < 4; j++) {
                p0[j] = __ldg((const __half2*)(xr0 + (size_t)tn * G4 + colbase + j * 8));
                p1[j] = __ldg((const __half2*)(xr1 + (size_t)tn * G4 + colbase + j * 8));
            }
        }

#pragma unroll
        for (int p = 0; p < 4; p++) {
            unsigned e0, e1, e2, e3, o0, o1, o2, o3;
            ldsm4(e0, e1, e2, e3, abase + (2 * p    ) * 32u);
            ldsm4(o0, o1, o2, o3, abase + (2 * p + 1) * 32u);
#pragma unroll
            for (int j = 0; j < 4; j++) {
                uint4 b = swfw[(j * 4 + p) * 32 + lane];
                mma16h(acc[j], e0, e1, e2, e3, b.x, b.y);
                mma16h(acc[j], o0, o1, o2, o3, b.z, b.w);
            }
        }

#pragma unroll
        for (int j = 0; j < 4; j++) {
            float a0 = odd ? tanh_ap(acc[j][0]) : sig_ap(acc[j][0]);
            float a1 = sig_ap(acc[j][1]);
            float a2 = odd ? tanh_ap(acc[j][2]) : sig_ap(acc[j][2]);
            float a3 = sig_ap(acc[j][3]);
            float sv0 = odd ? a0 : a2;
            float sv1 = odd ? a1 : a3;
            float rv0 = __shfl_xor_sync(0xffffffffu, sv0, 1);
            float rv1 = __shfl_xor_sync(0xffffffffu, sv1, 1);
            float iG = odd ? rv0 : a0;
            float fG = odd ? rv1 : a1;
            float gG = odd ? a2  : rv0;
            float oG = odd ? a3  : rv1;
            float cn = fG * c_reg[j] + iG * gG;
            float hn = oG * tanh_ap(cn);
            c_reg[j] = cn;
            int hh = hh0 + 2 * j;
            hnb[row_pw * SHh + hh] = __float2half_rn(hn);
            if (ts == T_STEPS - 1) hlast[(size_t)(b0 + row_pw) * H + hh] = hn;
        }
        __syncthreads();
        cur ^= 1;
    }
}

// ---------------- fused layer-0 LSTM: 16 recurrence warps + 8 projection warps ------------
// Proj warps read h_buf[cur] (= h0[ts-1], stable under double buffering), stream wih1 via
// __ldg, and emit xproj1[ts-1] in-place. The recurrence warps run the plain 230us loop.
__global__ void __launch_bounds__(768)
lstm_fused(const __half* __restrict__ xproj, const __half* __restrict__ wfh,
           const __half* __restrict__ wpf, __half* __restrict__ xpout,
           const float* __restrict__ biasp)
{
    extern __shared__ unsigned smx[];
    __half* h_buf = (__half*)smx;                          // [2][16*SHh]
    uint4*  swf   = (uint4*)((char*)smx + 2 * HBUF_B);     // whh: 8192 uint4 (128KB)

    const int tid  = threadIdx.x, lane = tid & 31, w = tid >> 5;
    const int g = lane >> 2, t = lane & 3;
    const int b0 = blockIdx.x * 16;

    // stage whh (flat copy) + zero h buffers
    {
        const uint4* src = (const uint4*)wfh;
        for (int idx = tid; idx < 16 * 512; idx += 768)
            swf[idx] = __ldg(src + idx);
    }
    for (int i = tid; i < (2 * HBUF_B) / 4; i += 768) smx[i] = 0u;
    __syncthreads();

    const unsigned hb_smem = (unsigned)__cvta_generic_to_shared(h_buf);
    const unsigned lmoff = hb_smem + (unsigned)((lane & 15) * SHh * 2 + (lane >> 4) * 16);

    if (w < 16) {
        // ---- recurrence warps (identical math to lstm_plain) ----
        const int odd = t & 1;
        uint4* swfw = swf + (size_t)w * 512;
        float c_reg[4] = {0.f, 0.f, 0.f, 0.f};
        const int row_pw = g + odd * 8;
        const int hh0    = w * 8 + (t >> 1);
        const __half* xr0 = xproj + (size_t)(b0 + g    ) * T_STEPS * G4;
        const __half* xr1 = xproj + (size_t)(b0 + g + 8) * T_STEPS * G4;
        const int colbase = w * 32 + 2 * t;

        __half2 p0[4], p1[4];
#pragma unroll
        for (int j = 0; j < 4; j++) {
            p0[j] = *(const __half2*)(xr0 + colbase + j * 8);
            p1[j] = *(const __half2*)(xr1 + colbase + j * 8);
        }

        int cur = 0;
        for (int ts = 0; ts < T_STEPS; ts++) {
            __half*        hnb   = h_buf + (cur ^ 1) * (16 * SHh);
            const unsigned abase = lmoff + (unsigned)(cur * HBUF_B);
            float acc[4][4];
#pragma unroll
            for (int j = 0; j < 4; j++) {
                float2 f0 = __half22float2(p0[j]);
                float2 f1 = __half22float2(p1[j]);
                acc[j][0] = f0.x; acc[j][1] = f0.y;
                acc[j][2] = f1.x; acc[j][3] = f1.y;
            }
            {
                int tn = (ts + 1 < T_STEPS) ? ts + 1 : ts;
#pragma unroll
                for (int j = 0; j < 4; j++) {
                    p0[j] = __ldg((const __half2*)(xr0 + (size_t)tn * G4 + colbase + j * 8));
                    p1[j] = __ldg((const __half2*)(xr1 + (size_t)tn * G4 + colbase + j * 8));
                }
            }

#pragma unroll
            for (int p = 0; p < 4; p++) {
                unsigned e0, e1, e2, e3, o0, o1, o2, o3;
                ldsm4(e0, e1, e2, e3, abase + (2 * p    ) * 32u);
                ldsm4(o0, o1, o2, o3, abase + (2 * p + 1) * 32u);
#pragma unroll
                for (int j = 0; j < 4; j++) {
                    uint4 b = swfw[(j * 4 + p) * 32 + lane];
                    mma16h(acc[j], e0, e1, e2, e3, b.x, b.y);
                    mma16h(acc[j], o0, o1, o2, o3, b.z, b.w);
                }
            }

#pragma unroll
            for (int j = 0; j < 4; j++) {
                float a0 = odd ? tanh_ap(acc[j][0]) : sig_ap(acc[j][0]);
                float a1 = sig_ap(acc[j][1]);
                float a2 = odd ? tanh_ap(acc[j][2]) : sig_ap(acc[j][2]);
                float a3 = sig_ap(acc[j][3]);
                float sv0 = odd ? a0 : a2;
                float sv1 = odd ? a1 : a3;
                float rv0 = __shfl_xor_sync(0xffffffffu, sv0, 1);
                float rv1 = __shfl_xor_sync(0xffffffffu, sv1, 1);
                float iG = odd ? rv0 : a0;
                float fG = odd ? rv1 : a1;
                float gG = odd ? a2  : rv0;
                float oG = odd ? a3  : rv1;
                float cn = fG * c_reg[j] + iG * gG;
                float hn = oG * tanh_ap(cn);
                c_reg[j] = cn;
                int hh = hh0 + 2 * j;
                hnb[row_pw * SHh + hh] = __float2half_rn(hn);
            }
            __syncthreads();
            cur ^= 1;
        }
    } else {
        // ---- projection warps: xproj1[ts-1] = h0[ts-1] @ wih1^T + bias ----
        const int pw = w - 16;                                   // 0..7, owns 64 cols
        __half* xw0 = xpout + (size_t)(b0 + g    ) * T_STEPS * G4;
        __half* xw1 = xpout + (size_t)(b0 + g + 8) * T_STEPS * G4;
        const uint4* wf4 = (const uint4*)wpf;

        auto EMIT = [&](int cur, int tsOut) {
            const unsigned abase = lmoff + (unsigned)(cur * HBUF_B);
            float pacc[8][4];
#pragma unroll
            for (int jj = 0; jj < 8; jj++)
#pragma unroll
                for (int q = 0; q < 4; q++) pacc[jj][q] = 0.f;
#pragma unroll
            for (int p = 0; p < 4; p++) {
                unsigned e0, e1, e2, e3, o0, o1, o2, o3;
                ldsm4(e0, e1, e2, e3, abase + (2 * p    ) * 32u);
                ldsm4(o0, o1, o2, o3, abase + (2 * p + 1) * 32u);
#pragma unroll
                for (int jj = 0; jj < 8; jj++) {
                    int nt = pw * 8 + jj;                        // tile 0..63
                    uint4 b = __ldg(wf4 + ((size_t)nt * 4 + p) * 32 + lane);
                    mma16h(pacc[jj], e0, e1, e2, e3, b.x, b.y);
                    mma16h(pacc[jj], o0, o1, o2, o3, b.z, b.w);
                }
            }
            size_t tb = (size_t)tsOut * G4;
#pragma unroll
            for (int jj = 0; jj < 8; jj++) {
                int col = (pw * 8 + jj) * 8 + 2 * t;
                float be0 = __ldg(biasp + col);
                float be1 = __ldg(biasp + col + 1);
                *(__half2*)(xw0 + tb + col) =
                    __floats2half2_rn(pacc[jj][0] + be0, pacc[jj][1] + be1);
                *(__half2*)(xw1 + tb + col) =
                    __floats2half2_rn(pacc[jj][2] + be0, pacc[jj][3] + be1);
            }
        };

        int cur = 0;
        for (int ts = 0; ts < T_STEPS; ts++) {
            if (ts > 0) EMIT(cur, ts - 1);
            __syncthreads();
            cur ^= 1;
        }
        EMIT(cur, T_STEPS - 1);   // tail: h0[T-1] is in h_buf[cur]
    }
}

// ---------------- launcher ----------------
extern "C" void kernel_launch(void* const* d_in, const int* in_sizes, int n_in,
                              void* d_out, int out_size)
{
    const float* x       = (const float*)d_in[0];
    const float* fc_w    = (const float*)d_in[1];
    const float* fc_b    = (const float*)d_in[2];
    const float* bn_g    = (const float*)d_in[3];
    const float* bn_b    = (const float*)d_in[4];
    const float* bn_mean = (const float*)d_in[5];
    const float* bn_var  = (const float*)d_in[6];
    const float* wih0    = (const float*)d_in[7];
    const float* whh0    = (const float*)d_in[8];
    const float* bih0    = (const float*)d_in[9];
    const float* bhh0    = (const float*)d_in[10];
    const float* wih1    = (const float*)d_in[11];
    const float* whh1    = (const float*)d_in[12];
    const float* bih1    = (const float*)d_in[13];
    const float* bhh1    = (const float*)d_in[14];
    float* out = (float*)d_out;

    const int B = in_sizes[0] / (F_IN * T_STEPS);
    const int M = B * T_STEPS;

    __half *p_xproj, *p_wfh0, *p_wfh1, *p_wifh0, *p_wifh1;
    float *p_biasp0, *p_biasp1;
    cudaGetSymbolAddress((void**)&p_xproj,  g_xproj);
    cudaGetSymbolAddress((void**)&p_biasp0, g_biasp0);
    cudaGetSymbolAddress((void**)&p_biasp1, g_biasp1);
    cudaGetSymbolAddress((void**)&p_wfh0,   g_wfh0);
    cudaGetSymbolAddress((void**)&p_wfh1,   g_wfh1);
    cudaGetSymbolAddress((void**)&p_wifh0,  g_wifh0);
    cudaGetSymbolAddress((void**)&p_wifh1,  g_wifh1);

    const size_t lstm_smem = (size_t)2 * HBUF_B + 16 * 512 * 16;     // ~136.5KB
    const size_t fuse_smem = (size_t)(4 * 128 * SA + 128 * S2) * 2;  // ~75KB
    cudaFuncSetAttribute(lstm_fused, cudaFuncAttributeMaxDynamicSharedMemorySize, (int)lstm_smem);
    cudaFuncSetAttribute(lstm_plain, cudaFuncAttributeMaxDynamicSharedMemorySize, (int)lstm_smem);
    cudaFuncSetAttribute(fc_proj_fused, cudaFuncAttributeMaxDynamicSharedMemorySize, (int)fuse_smem);

    prep_kernel<<<256, 256>>>(wih0, bih0, bhh0, whh0, p_biasp0, p_wfh0, p_wifh0);
    prep_kernel<<<256, 256>>>(wih1, bih1, bhh1, whh1, p_biasp1, p_wfh1, p_wifh1);

    // fused FC+BN+LeakyReLU -> layer-0 projection (fp16 mma throughout)
    fc_proj_fused<<<M / 128, 256, fuse_smem>>>(x, fc_w, p_wifh0, p_xproj,
                                               fc_b, bn_g, bn_b, bn_mean, bn_var, p_biasp0);
    // layer-0 LSTM + warp-specialized layer-1 projection (in-place xproj rewrite)
    lstm_fused<<<B / 16, 768, lstm_smem>>>(p_xproj, p_wfh0, p_wifh1, p_xproj, p_biasp1);
    // layer-1 LSTM -> final hidden state (fp32 out)
    lstm_plain<<<B / 16, 512, lstm_smem>>>(p_xproj, p_wfh1, out);
}

// round 17
// speedup vs baseline: 1.1047x; 1.1047x over previous
#include <cuda_runtime.h>
#include <cuda_fp16.h>
#include <math.h>

#define T_STEPS 120
#define F_IN    180
#define H       128
#define G4      512
#define MAX_B   2048

// ---------------- static scratch ----------------
__device__ __half g_xproj[(size_t)MAX_B * T_STEPS * G4];   // fp16 projections (in-place reuse)
__device__ float  g_biasp0[G4],  g_biasp1[G4];
__device__ __align__(16) __half g_wfh0[G4 * H], g_wfh1[G4 * H];   // Whh fp16 m16n8k16 B-frags
__device__ __align__(16) __half g_wifh0[G4 * H], g_wifh1[G4 * H]; // wih fp16 m16n8k16 B-frags

// ---------------- helpers ----------------
__device__ __forceinline__ void mma16h(float* c, unsigned a0, unsigned a1, unsigned a2, unsigned a3,
                                       unsigned b0, unsigned b1) {
    asm volatile("mma.sync.aligned.m16n8k16.row.col.f32.f16.f16.f32 "
                 "{%0,%1,%2,%3}, {%4,%5,%6,%7}, {%8,%9}, {%0,%1,%2,%3};"
                 : "+f"(c[0]), "+f"(c[1]), "+f"(c[2]), "+f"(c[3])
                 : "r"(a0), "r"(a1), "r"(a2), "r"(a3), "r"(b0), "r"(b1));
}
__device__ __forceinline__ void ldsm4(unsigned& a0, unsigned& a1, unsigned& a2, unsigned& a3,
                                      unsigned addr) {
    asm volatile("ldmatrix.sync.aligned.m8n8.x4.shared.b16 {%0,%1,%2,%3}, [%4];"
                 : "=r"(a0), "=r"(a1), "=r"(a2), "=r"(a3) : "r"(addr));
}
__device__ __forceinline__ float tanh_ap(float x) {
    float y; asm("tanh.approx.f32 %0, %1;" : "=f"(y) : "f"(x)); return y;
}
__device__ __forceinline__ float sig_ap(float x) {
    return fmaf(0.5f, tanh_ap(0.5f * x), 0.5f);
}

// ---------------- prep: combine bias; pack Whh AND wih as fp16 m16n8k16 B-frags ----------------
__global__ void prep_kernel(const float* __restrict__ wih, const float* __restrict__ bih,
                            const float* __restrict__ bhh, const float* __restrict__ whh,
                            float* __restrict__ biasp, __half* __restrict__ wfh,
                            __half* __restrict__ wifh)
{
    int i = blockIdx.x * 256 + threadIdx.x;
    if (i < G4 * H) {
        int n = i >> 7, k = i & 127;
        if (k == 0) {
            int np = ((n & 127) << 2) | (n >> 7);
            biasp[np] = bih[n] + bhh[n];
        }
        int v2 = i & 7, lane = (i >> 3) & 31, p = (i >> 8) & 3, j = (i >> 10) & 3, w = i >> 12;
        int ks = 2 * p + (v2 >> 2);
        int kk = ks * 16 + (lane & 3) * 2 + (v2 & 1) + ((v2 >> 1) & 1) * 8;
        int np = w * 32 + j * 8 + (lane >> 2);
        int orig = ((np & 3) << 7) | (np >> 2);
        wfh [i] = __float2half_rn(whh[orig * H + kk]);
        wifh[i] = __float2half_rn(wih[orig * H + kk]);
    }
}

#define SA  40
#define S2  136

// ---------------- fused FC+BN+LeakyReLU -> layer-0 projection (all fp16 mma) ----------------
__global__ void __launch_bounds__(256)
fc_proj_fused(const float* __restrict__ x, const float* __restrict__ W,
              const __half* __restrict__ Wf, __half* __restrict__ C,
              const float* __restrict__ fcb, const float* __restrict__ bng,
              const float* __restrict__ bnb, const float* __restrict__ bnm,
              const float* __restrict__ bnv, const float* __restrict__ biasp)
{
    extern __shared__ __align__(16) char fsm[];
    __half* Ah = (__half*)fsm;              // [2][128*SA]
    __half* Bh = Ah + 2 * 128 * SA;         // [2][128*SA]
    __half* hp = Bh + 2 * 128 * SA;         // [128][S2]
    __shared__ int rowbase[128];

    const int tid  = threadIdx.x;
    const int lane = tid & 31, warp = tid >> 5;
    const int g = lane >> 2, t = lane & 3;
    const int wm = warp & 3, wn = warp >> 2;
    const int m0 = blockIdx.x * 128;

    if (tid < 128) {
        int m = m0 + tid; int b = m / T_STEPS;
        rowbase[tid] = b * (F_IN * T_STEPS) + (m - b * T_STEPS);
    }
    __syncthreads();

    const int r  = tid >> 1;
    const int hf = tid & 1;
    const int nc = 6;

    __half2 av2[8], wv2[8];
    auto LOAD = [&](int kc) {
#pragma unroll
        for (int i = 0; i < 8; i++) {
            int k = kc + hf * 16 + 2 * i;
            float x0 = (k     < F_IN) ? __ldg(x + rowbase[r] + k * T_STEPS)       : 0.f;
            float x1 = (k + 1 < F_IN) ? __ldg(x + rowbase[r] + (k + 1) * T_STEPS) : 0.f;
            av2[i] = __floats2half2_rn(x0, x1);
            float w0 = (k     < F_IN) ? __ldg(W + r * F_IN + k)     : 0.f;
            float w1 = (k + 1 < F_IN) ? __ldg(W + r * F_IN + k + 1) : 0.f;
            wv2[i] = __floats2half2_rn(w0, w1);
        }
    };
    auto STORE = [&](int s) {
#pragma unroll
        for (int i = 0; i < 8; i++) {
            *(__half2*)&Ah[s * 128 * SA + r * SA + hf * 16 + 2 * i] = av2[i];
            *(__half2*)&Bh[s * 128 * SA + r * SA + hf * 16 + 2 * i] = wv2[i];
        }
    };

    float acc[2][8][4];
#pragma unroll
    for (int mi = 0; mi < 2; mi++)
#pragma unroll
        for (int j = 0; j < 8; j++)
#pragma unroll
            for (int q = 0; q < 4; q++) acc[mi][j][q] = 0.f;

    const unsigned ah_smem = (unsigned)__cvta_generic_to_shared(Ah);
    const unsigned lm_a    = ah_smem + (unsigned)((lane & 15) * SA * 2 + (lane >> 4) * 16);

    LOAD(0); STORE(0); __syncthreads();

    for (int c = 0; c < nc; c++) {
        if (c + 1 < nc) LOAD((c + 1) * 32);
        const unsigned abuf = lm_a + (unsigned)((c & 1) * 128 * SA * 2);
        const __half* bs = Bh + (c & 1) * 128 * SA;
#pragma unroll
        for (int kq = 0; kq < 2; kq++) {
            unsigned a[2][4];
#pragma unroll
            for (int mi = 0; mi < 2; mi++)
                ldsm4(a[mi][0], a[mi][1], a[mi][2], a[mi][3],
                      abuf + (unsigned)((wm * 32 + mi * 16) * SA * 2 + kq * 32));
#pragma unroll
            for (int j = 0; j < 8; j++) {
                int row = wn * 64 + j * 8 + g;
                unsigned b0 = *(const unsigned*)&bs[row * SA + kq * 16 + 2 * t];
                unsigned b1 = *(const unsigned*)&bs[row * SA + kq * 16 + 2 * t + 8];
#pragma unroll
                for (int mi = 0; mi < 2; mi++)
                    mma16h(acc[mi][j], a[mi][0], a[mi][1], a[mi][2], a[mi][3], b0, b1);
            }
        }
        if (c + 1 < nc) STORE((c + 1) & 1);
        __syncthreads();
    }

#pragma unroll
    for (int j = 0; j < 8; j++) {
        int col = wn * 64 + j * 8 + 2 * t;
        float s0 = bng[col]     * rsqrtf(bnv[col]     + 1e-5f);
        float s1 = bng[col + 1] * rsqrtf(bnv[col + 1] + 1e-5f);
        float be0 = (fcb[col]     - bnm[col]    ) * s0 + bnb[col];
        float be1 = (fcb[col + 1] - bnm[col + 1]) * s1 + bnb[col + 1];
#pragma unroll
        for (int mi = 0; mi < 2; mi++) {
            int row = wm * 32 + mi * 16 + g;
            float v0 = acc[mi][j][0] * s0 + be0;
            float v1 = acc[mi][j][1] * s1 + be1;
            float v2 = acc[mi][j][2] * s0 + be0;
            float v3 = acc[mi][j][3] * s1 + be1;
            v0 = (v0 >= 0.f) ? v0 : 0.01f * v0;
            v1 = (v1 >= 0.f) ? v1 : 0.01f * v1;
            v2 = (v2 >= 0.f) ? v2 : 0.01f * v2;
            v3 = (v3 >= 0.f) ? v3 : 0.01f * v3;
            *(__half2*)&hp[(row    ) * S2 + col] = __floats2half2_rn(v0, v1);
            *(__half2*)&hp[(row + 8) * S2 + col] = __floats2half2_rn(v2, v3);
        }
    }
    __syncthreads();

    const uint4* wf4 = (const uint4*)Wf;
    const unsigned hp_smem = (unsigned)__cvta_generic_to_shared(hp);
    const unsigned lm_h    = hp_smem + (unsigned)((lane & 15) * S2 * 2 + (lane >> 4) * 16);
#pragma unroll 1
    for (int nch = 0; nch < 4; nch++) {
        float a2[2][8][4];
#pragma unroll
        for (int mi = 0; mi < 2; mi++)
#pragma unroll
            for (int j = 0; j < 8; j++)
#pragma unroll
                for (int q = 0; q < 4; q++) a2[mi][j][q] = 0.f;

#pragma unroll
        for (int p = 0; p < 4; p++) {
            unsigned e[2][4], o[2][4];
#pragma unroll
            for (int mi = 0; mi < 2; mi++) {
                unsigned rbase = lm_h + (unsigned)((wm * 32 + mi * 16) * S2 * 2);
                ldsm4(e[mi][0], e[mi][1], e[mi][2], e[mi][3], rbase + (2 * p    ) * 32u);
                ldsm4(o[mi][0], o[mi][1], o[mi][2], o[mi][3], rbase + (2 * p + 1) * 32u);
            }
#pragma unroll
            for (int j = 0; j < 8; j++) {
                int nt = nch * 16 + wn * 8 + j;
                uint4 b = __ldg(wf4 + ((size_t)nt * 4 + p) * 32 + lane);
#pragma unroll
                for (int mi = 0; mi < 2; mi++) {
                    mma16h(a2[mi][j], e[mi][0], e[mi][1], e[mi][2], e[mi][3], b.x, b.y);
                    mma16h(a2[mi][j], o[mi][0], o[mi][1], o[mi][2], o[mi][3], b.z, b.w);
                }
            }
        }
#pragma unroll
        for (int j = 0; j < 8; j++) {
            int col = nch * 128 + wn * 64 + j * 8 + 2 * t;
            float be0 = __ldg(biasp + col);
            float be1 = __ldg(biasp + col + 1);
#pragma unroll
            for (int mi = 0; mi < 2; mi++) {
                int row = m0 + wm * 32 + mi * 16 + g;
                *(__half2*)(C + (size_t)row * G4 + col) =
                    __floats2half2_rn(a2[mi][j][0] + be0, a2[mi][j][1] + be1);
                *(__half2*)(C + (size_t)(row + 8) * G4 + col) =
                    __floats2half2_rn(a2[mi][j][2] + be0, a2[mi][j][3] + be1);
            }
        }
    }
}

// ---------------- persistent fp16 LSTM; PROJ fuses the next layer's input projection --------
// PROJ path: byte-identical to round 14 (proven best). Non-PROJ path: software-pipelined
// (all 8 ldsm hoisted to step start; B LDS.128 double-buffered across p) — regs are free
// at 1 CTA/SM.
#define SHh    136
#define HBUF_B (16 * SHh * 2)

template<bool PROJ>
__global__ void __launch_bounds__(512)
lstm_tc(const __half* __restrict__ xproj, const __half* __restrict__ wfh,
        const __half* __restrict__ wpf, __half* __restrict__ xpout,
        const float* __restrict__ biasp, float* __restrict__ hlast)
{
    extern __shared__ unsigned smx[];
    __half* h_buf = (__half*)smx;                          // [2][16*SHh]
    uint4*  swf   = (uint4*)((char*)smx + 2 * HBUF_B);     // whh: 16 warps x 512 uint4
    uint4*  swf1  = swf + 16 * 512;                        // wih1 p=2,3: 16 warps x 256 uint4

    const int tid  = threadIdx.x, lane = tid & 31, w = tid >> 5;
    const int g = lane >> 2, t = lane & 3;
    const int odd = t & 1;
    const int b0 = blockIdx.x * 16;
    uint4* swfw  = swf  + (size_t)w * 512;
    uint4* swf1w = swf1 + (size_t)w * 256;
    const int colbase = w * 32 + 2 * t;
    const uint4* src1 = PROJ ? ((const uint4*)wpf + (size_t)w * 512 + lane) : nullptr;

    {
        const uint4* src = (const uint4*)wfh + (size_t)w * 512;
        for (int idx = lane; idx < 512; idx += 32)
            swfw[idx] = __ldg(src + idx);
    }
    if (PROJ) {
#pragma unroll
        for (int j = 0; j < 4; j++)
#pragma unroll
            for (int p = 2; p < 4; p++)
                swf1w[(j * 2 + p - 2) * 32 + lane] = __ldg(src1 + (j * 4 + p) * 32);
    }

    for (int i = tid; i < (2 * HBUF_B) / 4; i += 512) smx[i] = 0u;
    __syncthreads();

    float c_reg[4] = {0.f, 0.f, 0.f, 0.f};
    const int row_pw = g + odd * 8;
    const int hh0    = w * 8 + (t >> 1);
    const __half* xr0 = xproj + (size_t)(b0 + g    ) * T_STEPS * G4;
    const __half* xr1 = xproj + (size_t)(b0 + g + 8) * T_STEPS * G4;
    __half* xw0 = PROJ ? (xpout + (size_t)(b0 + g    ) * T_STEPS * G4) : nullptr;
    __half* xw1 = PROJ ? (xpout + (size_t)(b0 + g + 8) * T_STEPS * G4) : nullptr;

    const unsigned hb_smem = (unsigned)__cvta_generic_to_shared(h_buf);
    const unsigned lmoff = hb_smem + (unsigned)((lane & 15) * SHh * 2 + (lane >> 4) * 16);

    __half2 p0[4], p1[4];
#pragma unroll
    for (int j = 0; j < 4; j++) {
        p0[j] = *(const __half2*)(xr0 + colbase + j * 8);
        p1[j] = *(const __half2*)(xr1 + colbase + j * 8);
    }

    int cur = 0;
    for (int ts = 0; ts < T_STEPS; ts++) {
        __half*        hnb   = h_buf + (cur ^ 1) * (16 * SHh);
        const unsigned abase = lmoff + (unsigned)(cur * HBUF_B);
        float acc[4][4];
#pragma unroll
        for (int j = 0; j < 4; j++) {
            float2 f0 = __half22float2(p0[j]);
            float2 f1 = __half22float2(p1[j]);
            acc[j][0] = f0.x; acc[j][1] = f0.y;
            acc[j][2] = f1.x; acc[j][3] = f1.y;
        }
        {
            int tn = (ts + 1 < T_STEPS) ? ts + 1 : ts;
#pragma unroll
            for (int j = 0; j < 4; j++) {
                p0[j] = __ldg((const __half2*)(xr0 + (size_t)tn * G4 + colbase + j * 8));
                p1[j] = __ldg((const __half2*)(xr1 + (size_t)tn * G4 + colbase + j * 8));
            }
        }

        if (!PROJ) {
            // software-pipelined recurrence: hoist all ldsm, double-buffer B
            unsigned ae[8][4];
#pragma unroll
            for (int q = 0; q < 8; q++)
                ldsm4(ae[q][0], ae[q][1], ae[q][2], ae[q][3], abase + q * 32u);
            uint4 bb[4];
#pragma unroll
            for (int j = 0; j < 4; j++) bb[j] = swfw[(j * 4) * 32 + lane];
#pragma unroll
            for (int p = 0; p < 4; p++) {
                uint4 bn[4];
                if (p < 3) {
#pragma unroll
                    for (int j = 0; j < 4; j++) bn[j] = swfw[(j * 4 + p + 1) * 32 + lane];
                }
#pragma unroll
                for (int j = 0; j < 4; j++) {
                    mma16h(acc[j], ae[2*p][0], ae[2*p][1], ae[2*p][2], ae[2*p][3],
                           bb[j].x, bb[j].y);
                    mma16h(acc[j], ae[2*p+1][0], ae[2*p+1][1], ae[2*p+1][2], ae[2*p+1][3],
                           bb[j].z, bb[j].w);
                }
                if (p < 3) {
#pragma unroll
                    for (int j = 0; j < 4; j++) bb[j] = bn[j];
                }
            }
        } else {
            // round-14 fused loop (proven best for PROJ)
            float pacc[4][4];
#pragma unroll
            for (int j = 0; j < 4; j++)
#pragma unroll
                for (int q = 0; q < 4; q++) pacc[j][q] = 0.f;

#pragma unroll
            for (int p = 0; p < 4; p++) {
                unsigned e0, e1, e2, e3, o0, o1, o2, o3;
                ldsm4(e0, e1, e2, e3, abase + (2 * p    ) * 32u);
                ldsm4(o0, o1, o2, o3, abase + (2 * p + 1) * 32u);
#pragma unroll
                for (int j = 0; j < 4; j++) {
                    uint4 b = swfw[(j * 4 + p) * 32 + lane];
                    mma16h(acc[j], e0, e1, e2, e3, b.x, b.y);
                    mma16h(acc[j], o0, o1, o2, o3, b.z, b.w);
                }
#pragma unroll
                for (int j = 0; j < 4; j++) {
                    uint4 b1 = (p < 2) ? __ldg(src1 + (j * 4 + p) * 32)
                                       : swf1w[(j * 2 + p - 2) * 32 + lane];
                    mma16h(pacc[j], e0, e1, e2, e3, b1.x, b1.y);
                    mma16h(pacc[j], o0, o1, o2, o3, b1.z, b1.w);
                }
            }

            // emit xproj1[ts-1] (A-frags were h0[ts-1])
            if (ts > 0) {
                size_t tb = (size_t)(ts - 1) * G4;
#pragma unroll
                for (int j = 0; j < 4; j++) {
                    float be0 = __ldg(biasp + colbase + j * 8);
                    float be1 = __ldg(biasp + colbase + j * 8 + 1);
                    *(__half2*)(xw0 + tb + colbase + j * 8) =
                        __floats2half2_rn(pacc[j][0] + be0, pacc[j][1] + be1);
                    *(__half2*)(xw1 + tb + colbase + j * 8) =
                        __floats2half2_rn(pacc[j][2] + be0, pacc[j][3] + be1);
                }
            }
        }

        // activations (hw tanh) + pair-exchange + state update
#pragma unroll
        for (int j = 0; j < 4; j++) {
            float a0 = odd ? tanh_ap(acc[j][0]) : sig_ap(acc[j][0]);
            float a1 = sig_ap(acc[j][1]);
            float a2 = odd ? tanh_ap(acc[j][2]) : sig_ap(acc[j][2]);
            float a3 = sig_ap(acc[j][3]);
            float sv0 = odd ? a0 : a2;
            float sv1 = odd ? a1 : a3;
            float rv0 = __shfl_xor_sync(0xffffffffu, sv0, 1);
            float rv1 = __shfl_xor_sync(0xffffffffu, sv1, 1);
            float iG = odd ? rv0 : a0;
            float fG = odd ? rv1 : a1;
            float gG = odd ? a2  : rv0;
            float oG = odd ? a3  : rv1;
            float cn = fG * c_reg[j] + iG * gG;
            float hn = oG * tanh_ap(cn);
            c_reg[j] = cn;
            int hh = hh0 + 2 * j;
            hnb[row_pw * SHh + hh] = __float2half_rn(hn);
            if (hlast && ts == T_STEPS - 1) hlast[(size_t)(b0 + row_pw) * H + hh] = hn;
        }
        __syncthreads();
        cur ^= 1;
    }

    // tail: xproj1[T-1] from h0[T-1] (now in h_buf[cur])
    if (PROJ) {
        const unsigned abase = lmoff + (unsigned)(cur * HBUF_B);
        float pacc[4][4];
#pragma unroll
        for (int j = 0; j < 4; j++)
#pragma unroll
            for (int q = 0; q < 4; q++) pacc[j][q] = 0.f;
#pragma unroll
        for (int p = 0; p < 4; p++) {
            unsigned e0, e1, e2, e3, o0, o1, o2, o3;
            ldsm4(e0, e1, e2, e3, abase + (2 * p    ) * 32u);
            ldsm4(o0, o1, o2, o3, abase + (2 * p + 1) * 32u);
#pragma unroll
            for (int j = 0; j < 4; j++) {
                uint4 b1 = (p < 2) ? __ldg(src1 + (j * 4 + p) * 32)
                                   : swf1w[(j * 2 + p - 2) * 32 + lane];
                mma16h(pacc[j], e0, e1, e2, e3, b1.x, b1.y);
                mma16h(pacc[j], o0, o1, o2, o3, b1.z, b1.w);
            }
        }
        size_t tb = (size_t)(T_STEPS - 1) * G4;
#pragma unroll
        for (int j = 0; j < 4; j++) {
            float be0 = __ldg(biasp + colbase + j * 8);
            float be1 = __ldg(biasp + colbase + j * 8 + 1);
            *(__half2*)(xw0 + tb + colbase + j * 8) =
                __floats2half2_rn(pacc[j][0] + be0, pacc[j][1] + be1);
            *(__half2*)(xw1 + tb + colbase + j * 8) =
                __floats2half2_rn(pacc[j][2] + be0, pacc[j][3] + be1);
        }
    }
}

// ---------------- launcher ----------------
extern "C" void kernel_launch(void* const* d_in, const int* in_sizes, int n_in,
                              void* d_out, int out_size)
{
    const float* x       = (const float*)d_in[0];
    const float* fc_w    = (const float*)d_in[1];
    const float* fc_b    = (const float*)d_in[2];
    const float* bn_g    = (const float*)d_in[3];
    const float* bn_b    = (const float*)d_in[4];
    const float* bn_mean = (const float*)d_in[5];
    const float* bn_var  = (const float*)d_in[6];
    const float* wih0    = (const float*)d_in[7];
    const float* whh0    = (const float*)d_in[8];
    const float* bih0    = (const float*)d_in[9];
    const float* bhh0    = (const float*)d_in[10];
    const float* wih1    = (const float*)d_in[11];
    const float* whh1    = (const float*)d_in[12];
    const float* bih1    = (const float*)d_in[13];
    const float* bhh1    = (const float*)d_in[14];
    float* out = (float*)d_out;

    const int B = in_sizes[0] / (F_IN * T_STEPS);
    const int M = B * T_STEPS;

    __half *p_xproj, *p_wfh0, *p_wfh1, *p_wifh0, *p_wifh1;
    float *p_biasp0, *p_biasp1;
    cudaGetSymbolAddress((void**)&p_xproj,  g_xproj);
    cudaGetSymbolAddress((void**)&p_biasp0, g_biasp0);
    cudaGetSymbolAddress((void**)&p_biasp1, g_biasp1);
    cudaGetSymbolAddress((void**)&p_wfh0,   g_wfh0);
    cudaGetSymbolAddress((void**)&p_wfh1,   g_wfh1);
    cudaGetSymbolAddress((void**)&p_wifh0,  g_wifh0);
    cudaGetSymbolAddress((void**)&p_wifh1,  g_wifh1);

    const size_t smem_proj = (size_t)2 * HBUF_B + 16 * 512 * 16 + 16 * 256 * 16;  // ~200.5KB
    const size_t smem_base = (size_t)2 * HBUF_B + 16 * 512 * 16;                  // ~136.5KB
    const size_t fuse_smem = (size_t)(4 * 128 * SA + 128 * S2) * 2;               // ~75KB
    cudaFuncSetAttribute(lstm_tc<true>,  cudaFuncAttributeMaxDynamicSharedMemorySize, (int)smem_proj);
    cudaFuncSetAttribute(lstm_tc<false>, cudaFuncAttributeMaxDynamicSharedMemorySize, (int)smem_base);
    cudaFuncSetAttribute(fc_proj_fused,  cudaFuncAttributeMaxDynamicSharedMemorySize, (int)fuse_smem);

    prep_kernel<<<256, 256>>>(wih0, bih0, bhh0, whh0, p_biasp0, p_wfh0, p_wifh0);
    prep_kernel<<<256, 256>>>(wih1, bih1, bhh1, whh1, p_biasp1, p_wfh1, p_wifh1);

    // fused FC+BN+LeakyReLU -> layer-0 projection (fp16 mma throughout)
    fc_proj_fused<<<M / 128, 256, fuse_smem>>>(x, fc_w, p_wifh0, p_xproj,
                                               fc_b, bn_g, bn_b, bn_mean, bn_var, p_biasp0);
    // layer-0 LSTM with fused layer-1 projection (in-place xproj rewrite)
    lstm_tc<true><<<B / 16, 512, smem_proj>>>(p_xproj, p_wfh0, p_wifh1, p_xproj,
                                              p_biasp1, nullptr);
    // layer-1 LSTM -> final hidden state (fp32 out)
    lstm_tc<false><<<B / 16, 512, smem_base>>>(p_xproj, p_wfh1, nullptr, nullptr,
                                               nullptr, out);
}